// round 6
// baseline (speedup 1.0000x reference)
#include <cuda_runtime.h>
#include <cuda_bf16.h>
#include <math.h>

#define TT    8192
#define HD    1024
#define G4H   4096
#define NBLK  128               // 128 blocks * 4 warps/dir * 2 units/warp = 1024 units/dir
#define KREG  512               // k < 512 register-resident (4 float4 chunks/lane)
#define KSM   512               // k in [512,1024) in smem
// dynamic smem: weights[8 warps][8 rows][512] + hstage[2][1024]
#define OFF_HS    (8*8*KSM)             // float offset of h stage
#define SMEM_LSTM ((OFF_HS + 2*HD) * 4) // 139264 B

// ---------------- static device scratch ----------------
__device__ float    g_xg[2][TT][G4H];
__device__ float    g_h0[(size_t)TT*2048];
__device__ float    g_h1[(size_t)TT*2048];
__device__ float    g_feats[TT*5];
__device__ float    g_hbuf[2][2][HD];        // [dir][ping][H]
struct Ctr { unsigned v; unsigned pad[31]; };
__device__ Ctr      g_ctr2[2];               // one counter per direction, own 128B line

union F2 { float2 f; unsigned long long u; };

__device__ __forceinline__ unsigned ld_acq(const unsigned* p) {
    unsigned v;
    asm volatile("ld.acquire.gpu.global.u32 %0, [%1];" : "=r"(v) : "l"(p) : "memory");
    return v;
}
__device__ __forceinline__ void red_rel_add1(unsigned* p) {
    asm volatile("red.release.gpu.global.add.u32 [%0], 1;" :: "l"(p) : "memory");
}
__device__ __forceinline__ void bar_named(int id) {
    asm volatile("bar.sync %0, 128;" :: "r"(id) : "memory");
}
__device__ __forceinline__ void fma2(F2& acc, float ax, float ay, float bx, float by) {
    F2 a, b; a.f.x = ax; a.f.y = ay; b.f.x = bx; b.f.y = by;
    asm("fma.rn.f32x2 %0, %1, %2, %0;" : "+l"(acc.u) : "l"(a.u), "l"(b.u));
}

__global__ void init_kernel() {
    int i = blockIdx.x * blockDim.x + threadIdx.x;
    if (i < 2*2*HD) ((float*)g_hbuf)[i] = 0.f;
    if (i < 2) g_ctr2[i].v = 0u;
}

// ---------------- fp32 SGEMM, double-buffered, f32x2 FMA ----------------
#define BM 128
#define BN 128
#define BK 16
__global__ void __launch_bounds__(256) sgemm_bias(
    const float* __restrict__ A, const float* __restrict__ W,
    const float* __restrict__ b1, const float* __restrict__ b2,
    float* __restrict__ C, int M, int N, int K)
{
    __shared__ float As[2][BK][BM+4];
    __shared__ float Bs[2][BK][BN+4];
    const int tid = threadIdx.x;
    const int bm0 = blockIdx.y * BM;
    const int bn0 = blockIdx.x * BN;
    const int tx = tid & 15, ty = tid >> 4;
    const int lrow = tid >> 2;
    const int lc4  = (tid & 3) * 4;

    F2 acc[8][4];
    #pragma unroll
    for (int i = 0; i < 8; i++)
        #pragma unroll
        for (int j = 0; j < 4; j++) acc[i][j].u = 0ull;

    float4 ra[2], rb[2];
    #pragma unroll
    for (int h = 0; h < 2; h++) {
        int row = lrow + h*64;
        ra[h] = *(const float4*)(A + (size_t)(bm0+row)*K + lc4);
        rb[h] = *(const float4*)(W + (size_t)(bn0+row)*K + lc4);
    }
    #pragma unroll
    for (int h = 0; h < 2; h++) {
        int row = lrow + h*64;
        As[0][lc4+0][row] = ra[h].x; As[0][lc4+1][row] = ra[h].y;
        As[0][lc4+2][row] = ra[h].z; As[0][lc4+3][row] = ra[h].w;
        Bs[0][lc4+0][row] = rb[h].x; Bs[0][lc4+1][row] = rb[h].y;
        Bs[0][lc4+2][row] = rb[h].z; Bs[0][lc4+3][row] = rb[h].w;
    }
    __syncthreads();

    int buf = 0;
    for (int k0 = BK; k0 <= K; k0 += BK) {
        if (k0 < K) {
            #pragma unroll
            for (int h = 0; h < 2; h++) {
                int row = lrow + h*64;
                ra[h] = *(const float4*)(A + (size_t)(bm0+row)*K + k0 + lc4);
                rb[h] = *(const float4*)(W + (size_t)(bn0+row)*K + k0 + lc4);
            }
        }
        #pragma unroll
        for (int kk = 0; kk < BK; kk++) {
            float a[8]; F2 bp[4];
            #pragma unroll
            for (int i = 0; i < 8; i++) a[i] = As[buf][kk][ty*8+i];
            #pragma unroll
            for (int j = 0; j < 4; j++) bp[j].f = *(const float2*)&Bs[buf][kk][tx*8 + 2*j];
            #pragma unroll
            for (int i = 0; i < 8; i++) {
                F2 ap; ap.f.x = a[i]; ap.f.y = a[i];
                #pragma unroll
                for (int j = 0; j < 4; j++)
                    asm("fma.rn.f32x2 %0, %1, %2, %0;" : "+l"(acc[i][j].u) : "l"(ap.u), "l"(bp[j].u));
            }
        }
        if (k0 < K) {
            __syncthreads();
            int nb = buf ^ 1;
            #pragma unroll
            for (int h = 0; h < 2; h++) {
                int row = lrow + h*64;
                As[nb][lc4+0][row] = ra[h].x; As[nb][lc4+1][row] = ra[h].y;
                As[nb][lc4+2][row] = ra[h].z; As[nb][lc4+3][row] = ra[h].w;
                Bs[nb][lc4+0][row] = rb[h].x; Bs[nb][lc4+1][row] = rb[h].y;
                Bs[nb][lc4+2][row] = rb[h].z; Bs[nb][lc4+3][row] = rb[h].w;
            }
            __syncthreads();
            buf = nb;
        }
    }
    float bv[8];
    #pragma unroll
    for (int j = 0; j < 8; j++) { int n = bn0 + tx*8 + j; bv[j] = b1[n] + b2[n]; }
    #pragma unroll
    for (int i = 0; i < 8; i++) {
        size_t mrow = (size_t)(bm0 + ty*8 + i) * N;
        #pragma unroll
        for (int j = 0; j < 4; j++) {
            C[mrow + bn0 + tx*8 + 2*j + 0] = acc[i][j].f.x + bv[2*j+0];
            C[mrow + bn0 + tx*8 + 2*j + 1] = acc[i][j].f.y + bv[2*j+1];
        }
    }
}

// ---------------- persistent bidirectional LSTM layer ----------------
// 128 blocks x 8 warps. Warp w: dir=w>>2, gq=w&3, owns units u0=b*8+gq*2 +{0,1},
// i.e. 8 whole gate rows (r = gate*2 + du). Per step: warp-converged poll ->
// group stages h into smem -> ONE named barrier -> per-warp dots (reg+smem
// weights, f32x2) -> butterfly reduce -> lanes 0/1 combine + store + arrive.
__global__ void __launch_bounds__(256, 1) lstm_kernel(
    const float* __restrict__ xgf, const float* __restrict__ xgb,
    const float* __restrict__ whf, const float* __restrict__ whb,
    float* __restrict__ hout)
{
    extern __shared__ float ws[];
    const int tid  = threadIdx.x;
    const int warp = tid >> 5;
    const int lane = tid & 31;
    const int dir  = warp >> 2;
    const int gq   = warp & 3;
    const int gtid = tid & 127;
    const int u0   = blockIdx.x * 8 + gq * 2;

    const float* wh = dir ? whb : whf;
    const float* xg = dir ? xgb : xgf;

    // ---- stage smem weight half (k in [512,1024)), whole block cooperates ----
    for (int idx = tid; idx < 8*8*(KSM/4); idx += 256) {
        int w2 = idx >> 10;                 // warp slot 0..7
        int rr = (idx >> 7) & 7;            // row within warp
        int q  = idx & 127;                 // float4 within KSM
        int unit = blockIdx.x * 8 + (w2 & 3) * 2 + (rr & 1);
        int gate = rr >> 1;
        const float* src = ((w2 >> 2) ? whb : whf) + ((size_t)((gate << 10) + unit)) * HD;
        ((float4*)ws)[idx] = __ldg((const float4*)src + (KREG/4) + q);
    }
    // ---- register weight half (k < 512): wreg[8 rows][4 chunks] ----
    float4 wreg[8][4];
    #pragma unroll
    for (int r = 0; r < 8; r++) {
        int unit = u0 + (r & 1);
        int gate = r >> 1;
        const float4* src = (const float4*)(wh + ((size_t)((gate << 10) + unit)) * HD);
        #pragma unroll
        for (int i = 0; i < 4; i++) wreg[r][i] = __ldg(src + (i << 5) + lane);
    }
    __syncthreads();

    const float4* ws_warp = (const float4*)ws + warp * 8 * (KSM/4);
    float4* hs4 = (float4*)(ws + OFF_HS + dir * HD);
    const bool cl = (lane < 2);
    const int  myu = u0 + lane;             // lanes 0,1
    unsigned* ctr = &g_ctr2[dir].v;
    const int bid = 1 + dir;
    float creg = 0.f;

    #pragma unroll 1
    for (int t = 0; t < TT; t++) {
        const int tt = dir ? (TT-1-t) : t;
        // xg prefetch for lanes 0,1 (DRAM, issued before poll)
        float xgv0=0.f, xgv1=0.f, xgv2=0.f, xgv3=0.f;
        if (cl) {
            const float* p = xg + (size_t)tt * G4H + myu;
            xgv0 = __ldg(p); xgv1 = __ldg(p+HD); xgv2 = __ldg(p+2*HD); xgv3 = __ldg(p+3*HD);
        }
        // warp-converged poll (single L2 line, one request per warp)
        {
            const unsigned tgt = (unsigned)t * 1024u;   // 128 blk * 4 warps * 2 lanes per dir
            while (ld_acq(ctr) < tgt) { }
        }
        // group stages h into smem: 256 float4 over 128 threads
        {
            const float4* hb4 = (const float4*)&g_hbuf[dir][t & 1][0];
            hs4[gtid]       = __ldcg(hb4 + gtid);
            hs4[gtid + 128] = __ldcg(hb4 + gtid + 128);
        }
        bar_named(bid);
        // h into registers from smem
        float4 hv[8];
        #pragma unroll
        for (int i = 0; i < 8; i++) hv[i] = hs4[(i << 5) + lane];
        // 8 complete gate-row dots: 4 chunks regs + 4 chunks smem, f32x2
        F2 acc[8];
        #pragma unroll
        for (int r = 0; r < 8; r++) acc[r].u = 0ull;
        #pragma unroll
        for (int r = 0; r < 8; r++) {
            #pragma unroll
            for (int i = 0; i < 4; i++) {
                float4 w = wreg[r][i];
                fma2(acc[r], w.x, w.y, hv[i].x, hv[i].y);
                fma2(acc[r], w.z, w.w, hv[i].z, hv[i].w);
            }
            const float4* w4s = ws_warp + r * (KSM/4);
            #pragma unroll
            for (int i = 0; i < 4; i++) {
                float4 v = w4s[(i << 5) + lane];
                fma2(acc[r], v.x, v.y, hv[4+i].x, hv[4+i].y);
                fma2(acc[r], v.z, v.w, hv[4+i].z, hv[4+i].w);
            }
        }
        // butterfly reduce: every lane gets all 8 row sums
        float v[8];
        #pragma unroll
        for (int r = 0; r < 8; r++) {
            float s = acc[r].f.x + acc[r].f.y;
            #pragma unroll
            for (int off = 16; off; off >>= 1) s += __shfl_xor_sync(0xFFFFFFFFu, s, off);
            v[r] = s;
        }
        // combine: lane 0 -> u0, lane 1 -> u0+1 (row r = gate*2 + lane)
        if (cl) {
            float gi = xgv0 + v[0 + lane];
            float gf = xgv1 + v[2 + lane];
            float gg = xgv2 + v[4 + lane];
            float go = xgv3 + v[6 + lane];
            float si = 1.f / (1.f + expf(-gi));
            float sf = 1.f / (1.f + expf(-gf));
            float so = 1.f / (1.f + expf(-go));
            creg = sf * creg + si * tanhf(gg);
            float h = so * tanhf(creg);
            __stcg(&g_hbuf[dir][(t+1) & 1][myu], h);
            hout[(size_t)tt * 2048 + (dir << 10) + myu] = h;
            red_rel_add1(ctr);   // per-lane release orders this lane's store
        }
    }
}

// ---------------- feats = h1 @ w_out^T + b_out ----------------
__global__ void feats_kernel(const float* __restrict__ h1, const float* __restrict__ wout,
                             const float* __restrict__ bout, float* __restrict__ feats)
{
    __shared__ float red[5][256];
    int t = blockIdx.x, tid = threadIdx.x;
    const float* hrow = h1 + (size_t)t * 2048;
    float p0=0,p1=0,p2=0,p3=0,p4=0;
    for (int k = tid; k < 2048; k += 256) {
        float hv = hrow[k];
        p0 = fmaf(hv, __ldg(wout + 0*2048 + k), p0);
        p1 = fmaf(hv, __ldg(wout + 1*2048 + k), p1);
        p2 = fmaf(hv, __ldg(wout + 2*2048 + k), p2);
        p3 = fmaf(hv, __ldg(wout + 3*2048 + k), p3);
        p4 = fmaf(hv, __ldg(wout + 4*2048 + k), p4);
    }
    red[0][tid]=p0; red[1][tid]=p1; red[2][tid]=p2; red[3][tid]=p3; red[4][tid]=p4;
    __syncthreads();
    if (tid < 5) {
        float s = 0.f;
        for (int i = 0; i < 256; i++) s += red[tid][i];
        feats[t*5 + tid] = s + bout[tid];
    }
}

// ---------------- Viterbi DP + backtrace ----------------
#define NEGV (-10000.0f)
__global__ void viterbi_kernel(const float* __restrict__ feats, const float* __restrict__ trans,
                               float* __restrict__ out, int out_size)
{
    __shared__ unsigned char bp[TT*5];
    __shared__ float fch[256*5];
    const int lane = threadIdx.x;
    float trow[5] = {0,0,0,0,0};
    if (lane < 5) {
        #pragma unroll
        for (int p = 0; p < 5; p++) trow[p] = trans[lane*5 + p];
    }
    float fv[5];
    #pragma unroll
    for (int p = 0; p < 5; p++) fv[p] = (p == 3) ? 0.f : NEGV;

    for (int ch = 0; ch < TT/256; ch++) {
        const float* src = feats + ch*256*5;
        for (int i = lane; i < 256*5; i += 32) fch[i] = src[i];
        __syncwarp();
        for (int s = 0; s < 256; s++) {
            float best = fv[0] + trow[0]; int arg = 0;
            #pragma unroll
            for (int p = 1; p < 5; p++) { float v = fv[p] + trow[p]; if (v > best) { best = v; arg = p; } }
            float fe = (lane < 5) ? fch[s*5 + lane] : 0.f;
            float nv = best + fe;
            if (lane < 5) bp[(ch*256 + s)*5 + lane] = (unsigned char)arg;
            #pragma unroll
            for (int p = 0; p < 5; p++) fv[p] = __shfl_sync(0xFFFFFFFFu, nv, p);
        }
        __syncwarp();
    }
    float term = (lane < 5) ? (fv[lane] + trans[4*5 + lane]) : (4.f*NEGV);
    float t0 = __shfl_sync(0xFFFFFFFFu, term, 0);
    float t1 = __shfl_sync(0xFFFFFFFFu, term, 1);
    float t2 = __shfl_sync(0xFFFFFFFFu, term, 2);
    float t3 = __shfl_sync(0xFFFFFFFFu, term, 3);
    float t4 = __shfl_sync(0xFFFFFFFFu, term, 4);
    if (lane == 0) {
        float best = t0; int lbl = 0;
        if (t1 > best) { best = t1; lbl = 1; }
        if (t2 > best) { best = t2; lbl = 2; }
        if (t3 > best) { best = t3; lbl = 3; }
        if (t4 > best) { best = t4; lbl = 4; }
        if (out_size >= TT + 1) {
            int base = out_size - TT;
            out[0] = best;
            out[base + TT - 1] = (float)lbl;
            for (int t = TT - 2; t >= 0; t--) { lbl = bp[(t+1)*5 + lbl]; out[base + t] = (float)lbl; }
        } else if (out_size >= TT) {
            int base = out_size - TT;
            out[base + TT - 1] = (float)lbl;
            for (int t = TT - 2; t >= 0; t--) { lbl = bp[(t+1)*5 + lbl]; out[base + t] = (float)lbl; }
        } else if (out_size >= 1) {
            out[0] = best;
        }
    }
}

// ---------------- host launch ----------------
extern "C" void kernel_launch(void* const* d_in, const int* in_sizes, int n_in,
                              void* d_out, int out_size)
{
    const float* hours    = (const float*)d_in[0];
    const float* w_ih_l0  = (const float*)d_in[1];
    const float* w_hh_l0  = (const float*)d_in[2];
    const float* b_ih_l0  = (const float*)d_in[3];
    const float* b_hh_l0  = (const float*)d_in[4];
    const float* w_ih_l0r = (const float*)d_in[5];
    const float* w_hh_l0r = (const float*)d_in[6];
    const float* b_ih_l0r = (const float*)d_in[7];
    const float* b_hh_l0r = (const float*)d_in[8];
    const float* w_ih_l1  = (const float*)d_in[9];
    const float* w_hh_l1  = (const float*)d_in[10];
    const float* b_ih_l1  = (const float*)d_in[11];
    const float* b_hh_l1  = (const float*)d_in[12];
    const float* w_ih_l1r = (const float*)d_in[13];
    const float* w_hh_l1r = (const float*)d_in[14];
    const float* b_ih_l1r = (const float*)d_in[15];
    const float* b_hh_l1r = (const float*)d_in[16];
    const float* w_out    = (const float*)d_in[17];
    const float* b_out    = (const float*)d_in[18];
    const float* trans    = (const float*)d_in[19];

    float *xg0, *h0, *h1, *feats;
    cudaGetSymbolAddress((void**)&xg0,   g_xg);
    cudaGetSymbolAddress((void**)&h0,    g_h0);
    cudaGetSymbolAddress((void**)&h1,    g_h1);
    cudaGetSymbolAddress((void**)&feats, g_feats);
    float* xg1 = xg0 + (size_t)TT * G4H;

    cudaFuncSetAttribute(lstm_kernel, cudaFuncAttributeMaxDynamicSharedMemorySize, SMEM_LSTM);

    dim3 gemm_grid(G4H/BN, TT/BM);

    sgemm_bias<<<gemm_grid, 256>>>(hours, w_ih_l0,  b_ih_l0,  b_hh_l0,  xg0, TT, G4H, 512);
    sgemm_bias<<<gemm_grid, 256>>>(hours, w_ih_l0r, b_ih_l0r, b_hh_l0r, xg1, TT, G4H, 512);
    init_kernel<<<16, 256>>>();
    lstm_kernel<<<NBLK, 256, SMEM_LSTM>>>(xg0, xg1, w_hh_l0, w_hh_l0r, h0);

    sgemm_bias<<<gemm_grid, 256>>>(h0, w_ih_l1,  b_ih_l1,  b_hh_l1,  xg0, TT, G4H, 2048);
    sgemm_bias<<<gemm_grid, 256>>>(h0, w_ih_l1r, b_ih_l1r, b_hh_l1r, xg1, TT, G4H, 2048);
    init_kernel<<<16, 256>>>();
    lstm_kernel<<<NBLK, 256, SMEM_LSTM>>>(xg0, xg1, w_hh_l1, w_hh_l1r, h1);

    feats_kernel<<<TT, 256>>>(h1, w_out, b_out, feats);
    viterbi_kernel<<<1, 32>>>(feats, trans, (float*)d_out, out_size);
}

// round 7
// speedup vs baseline: 1.3493x; 1.3493x over previous
#include <cuda_runtime.h>
#include <cuda_bf16.h>
#include <math.h>

#define TT    8192
#define HD    1024
#define G4H   4096
#define NBLK  128               // 128 blocks * 4 warps/dir * 2 units/warp = 1024 units/dir
#define KREG  512               // k < 512 register-resident (4 float4 chunks/lane)
#define KSM   512               // k in [512,1024) in smem
// dynamic smem: weights[8 warps][8 rows][512] + hstage[2][1024]
#define OFF_HS    (8*8*KSM)             // float offset of h stage
#define SMEM_LSTM ((OFF_HS + 2*HD) * 4) // 139264 B

// ---------------- static device scratch ----------------
__device__ float    g_xg[2][TT][G4H];
__device__ float    g_h0[(size_t)TT*2048];
__device__ float    g_h1[(size_t)TT*2048];
__device__ float    g_feats[TT*5];
__device__ float    g_hbuf[2][2][HD];        // [dir][ping][H]
struct Ctr { unsigned v; unsigned pad[31]; };
__device__ Ctr      g_ctr2[2];               // one counter per direction, own 128B line

union F2 { float2 f; unsigned long long u; };

__device__ __forceinline__ unsigned ld_acq(const unsigned* p) {
    unsigned v;
    asm volatile("ld.acquire.gpu.global.u32 %0, [%1];" : "=r"(v) : "l"(p) : "memory");
    return v;
}
__device__ __forceinline__ void red_rel_add1(unsigned* p) {
    asm volatile("red.release.gpu.global.add.u32 [%0], 1;" :: "l"(p) : "memory");
}
__device__ __forceinline__ void bar_named(int id) {
    asm volatile("bar.sync %0, 128;" :: "r"(id) : "memory");
}
__device__ __forceinline__ void fma2(F2& acc, float ax, float ay, float bx, float by) {
    F2 a, b; a.f.x = ax; a.f.y = ay; b.f.x = bx; b.f.y = by;
    asm("fma.rn.f32x2 %0, %1, %2, %0;" : "+l"(acc.u) : "l"(a.u), "l"(b.u));
}

__global__ void init_kernel() {
    int i = blockIdx.x * blockDim.x + threadIdx.x;
    if (i < 2*2*HD) ((float*)g_hbuf)[i] = 0.f;
    if (i < 2) g_ctr2[i].v = 0u;
}

// ---------------- fp32 SGEMM, double-buffered, f32x2 FMA ----------------
#define BM 128
#define BN 128
#define BK 16
__global__ void __launch_bounds__(256) sgemm_bias(
    const float* __restrict__ A, const float* __restrict__ W,
    const float* __restrict__ b1, const float* __restrict__ b2,
    float* __restrict__ C, int M, int N, int K)
{
    __shared__ float As[2][BK][BM+4];
    __shared__ float Bs[2][BK][BN+4];
    const int tid = threadIdx.x;
    const int bm0 = blockIdx.y * BM;
    const int bn0 = blockIdx.x * BN;
    const int tx = tid & 15, ty = tid >> 4;
    const int lrow = tid >> 2;
    const int lc4  = (tid & 3) * 4;

    F2 acc[8][4];
    #pragma unroll
    for (int i = 0; i < 8; i++)
        #pragma unroll
        for (int j = 0; j < 4; j++) acc[i][j].u = 0ull;

    float4 ra[2], rb[2];
    #pragma unroll
    for (int h = 0; h < 2; h++) {
        int row = lrow + h*64;
        ra[h] = *(const float4*)(A + (size_t)(bm0+row)*K + lc4);
        rb[h] = *(const float4*)(W + (size_t)(bn0+row)*K + lc4);
    }
    #pragma unroll
    for (int h = 0; h < 2; h++) {
        int row = lrow + h*64;
        As[0][lc4+0][row] = ra[h].x; As[0][lc4+1][row] = ra[h].y;
        As[0][lc4+2][row] = ra[h].z; As[0][lc4+3][row] = ra[h].w;
        Bs[0][lc4+0][row] = rb[h].x; Bs[0][lc4+1][row] = rb[h].y;
        Bs[0][lc4+2][row] = rb[h].z; Bs[0][lc4+3][row] = rb[h].w;
    }
    __syncthreads();

    int buf = 0;
    for (int k0 = BK; k0 <= K; k0 += BK) {
        if (k0 < K) {
            #pragma unroll
            for (int h = 0; h < 2; h++) {
                int row = lrow + h*64;
                ra[h] = *(const float4*)(A + (size_t)(bm0+row)*K + k0 + lc4);
                rb[h] = *(const float4*)(W + (size_t)(bn0+row)*K + k0 + lc4);
            }
        }
        #pragma unroll
        for (int kk = 0; kk < BK; kk++) {
            float a[8]; F2 bp[4];
            #pragma unroll
            for (int i = 0; i < 8; i++) a[i] = As[buf][kk][ty*8+i];
            #pragma unroll
            for (int j = 0; j < 4; j++) bp[j].f = *(const float2*)&Bs[buf][kk][tx*8 + 2*j];
            #pragma unroll
            for (int i = 0; i < 8; i++) {
                F2 ap; ap.f.x = a[i]; ap.f.y = a[i];
                #pragma unroll
                for (int j = 0; j < 4; j++)
                    asm("fma.rn.f32x2 %0, %1, %2, %0;" : "+l"(acc[i][j].u) : "l"(ap.u), "l"(bp[j].u));
            }
        }
        if (k0 < K) {
            __syncthreads();
            int nb = buf ^ 1;
            #pragma unroll
            for (int h = 0; h < 2; h++) {
                int row = lrow + h*64;
                As[nb][lc4+0][row] = ra[h].x; As[nb][lc4+1][row] = ra[h].y;
                As[nb][lc4+2][row] = ra[h].z; As[nb][lc4+3][row] = ra[h].w;
                Bs[nb][lc4+0][row] = rb[h].x; Bs[nb][lc4+1][row] = rb[h].y;
                Bs[nb][lc4+2][row] = rb[h].z; Bs[nb][lc4+3][row] = rb[h].w;
            }
            __syncthreads();
            buf = nb;
        }
    }
    float bv[8];
    #pragma unroll
    for (int j = 0; j < 8; j++) { int n = bn0 + tx*8 + j; bv[j] = b1[n] + b2[n]; }
    #pragma unroll
    for (int i = 0; i < 8; i++) {
        size_t mrow = (size_t)(bm0 + ty*8 + i) * N;
        #pragma unroll
        for (int j = 0; j < 4; j++) {
            C[mrow + bn0 + tx*8 + 2*j + 0] = acc[i][j].f.x + bv[2*j+0];
            C[mrow + bn0 + tx*8 + 2*j + 1] = acc[i][j].f.y + bv[2*j+1];
        }
    }
}

// ---------------- persistent bidirectional LSTM layer ----------------
// 128 blocks x 8 warps. Warp w: dir=w>>2, gq=w&3, owns units u0=b*8+gq*2 +{0,1},
// i.e. 8 whole gate rows (r = gate*2 + du). Per step:
//   warp-converged poll (nanosleep backoff) -> group stages h to smem -> bar ->
//   per-warp dots (reg+smem weights, f32x2) -> butterfly reduce ->
//   lanes 0/1 combine + stcg hbuf -> threadfence -> bar -> ONE red.release/block/dir
//   -> hout DRAM store (off critical path).
__global__ void __launch_bounds__(256, 1) lstm_kernel(
    const float* __restrict__ xgf, const float* __restrict__ xgb,
    const float* __restrict__ whf, const float* __restrict__ whb,
    float* __restrict__ hout)
{
    extern __shared__ float ws[];
    const int tid  = threadIdx.x;
    const int warp = tid >> 5;
    const int lane = tid & 31;
    const int dir  = warp >> 2;
    const int gq   = warp & 3;
    const int gtid = tid & 127;
    const int u0   = blockIdx.x * 8 + gq * 2;

    const float* wh = dir ? whb : whf;
    const float* xg = dir ? xgb : xgf;

    // ---- stage smem weight half (k in [512,1024)), whole block cooperates ----
    for (int idx = tid; idx < 8*8*(KSM/4); idx += 256) {
        int w2 = idx >> 10;                 // warp slot 0..7
        int rr = (idx >> 7) & 7;            // row within warp
        int q  = idx & 127;                 // float4 within KSM
        int unit = blockIdx.x * 8 + (w2 & 3) * 2 + (rr & 1);
        int gate = rr >> 1;
        const float* src = ((w2 >> 2) ? whb : whf) + ((size_t)((gate << 10) + unit)) * HD;
        ((float4*)ws)[idx] = __ldg((const float4*)src + (KREG/4) + q);
    }
    // ---- register weight half (k < 512): wreg[8 rows][4 chunks] ----
    float4 wreg[8][4];
    #pragma unroll
    for (int r = 0; r < 8; r++) {
        int unit = u0 + (r & 1);
        int gate = r >> 1;
        const float4* src = (const float4*)(wh + ((size_t)((gate << 10) + unit)) * HD);
        #pragma unroll
        for (int i = 0; i < 4; i++) wreg[r][i] = __ldg(src + (i << 5) + lane);
    }
    __syncthreads();

    const float4* ws_warp = (const float4*)ws + warp * 8 * (KSM/4);
    float4* hs4 = (float4*)(ws + OFF_HS + dir * HD);
    const bool cl = (lane < 2);
    const int  myu = u0 + lane;             // lanes 0,1
    unsigned* ctr = &g_ctr2[dir].v;
    const int bid = 1 + dir;
    float creg = 0.f;

    #pragma unroll 1
    for (int t = 0; t < TT; t++) {
        const int tt = dir ? (TT-1-t) : t;
        // xg prefetch for lanes 0,1 (DRAM, issued before poll)
        float xgv0=0.f, xgv1=0.f, xgv2=0.f, xgv3=0.f;
        if (cl) {
            const float* p = xg + (size_t)tt * G4H + myu;
            xgv0 = __ldg(p); xgv1 = __ldg(p+HD); xgv2 = __ldg(p+2*HD); xgv3 = __ldg(p+3*HD);
        }
        // warp-converged poll with backoff (one L2 read per warp per iter)
        {
            const unsigned tgt = (unsigned)t * (unsigned)NBLK;  // 1 arrival/block/dir
            unsigned v = ld_acq(ctr);
            while (v < tgt) { __nanosleep(40); v = ld_acq(ctr); }
        }
        // group stages h into smem: 256 float4 over 128 threads
        {
            const float4* hb4 = (const float4*)&g_hbuf[dir][t & 1][0];
            hs4[gtid]       = __ldcg(hb4 + gtid);
            hs4[gtid + 128] = __ldcg(hb4 + gtid + 128);
        }
        bar_named(bid);
        // h into registers from smem
        float4 hv[8];
        #pragma unroll
        for (int i = 0; i < 8; i++) hv[i] = hs4[(i << 5) + lane];
        // 8 complete gate-row dots: 4 chunks regs + 4 chunks smem, f32x2
        F2 acc[8];
        #pragma unroll
        for (int r = 0; r < 8; r++) acc[r].u = 0ull;
        #pragma unroll
        for (int r = 0; r < 8; r++) {
            #pragma unroll
            for (int i = 0; i < 4; i++) {
                float4 w = wreg[r][i];
                fma2(acc[r], w.x, w.y, hv[i].x, hv[i].y);
                fma2(acc[r], w.z, w.w, hv[i].z, hv[i].w);
            }
            const float4* w4s = ws_warp + r * (KSM/4);
            #pragma unroll
            for (int i = 0; i < 4; i++) {
                float4 v = w4s[(i << 5) + lane];
                fma2(acc[r], v.x, v.y, hv[4+i].x, hv[4+i].y);
                fma2(acc[r], v.z, v.w, hv[4+i].z, hv[4+i].w);
            }
        }
        // butterfly reduce: every lane gets all 8 row sums
        float v[8];
        #pragma unroll
        for (int r = 0; r < 8; r++) {
            float s = acc[r].f.x + acc[r].f.y;
            #pragma unroll
            for (int off = 16; off; off >>= 1) s += __shfl_xor_sync(0xFFFFFFFFu, s, off);
            v[r] = s;
        }
        // combine: lane 0 -> u0, lane 1 -> u0+1 (row r = gate*2 + lane)
        float h = 0.f;
        if (cl) {
            float gi = xgv0 + v[0 + lane];
            float gf = xgv1 + v[2 + lane];
            float gg = xgv2 + v[4 + lane];
            float go = xgv3 + v[6 + lane];
            float si = 1.f / (1.f + expf(-gi));
            float sf = 1.f / (1.f + expf(-gf));
            float so = 1.f / (1.f + expf(-go));
            creg = sf * creg + si * tanhf(gg);
            h = so * tanhf(creg);
            __stcg(&g_hbuf[dir][(t+1) & 1][myu], h);
            __threadfence();                 // order hbuf store before group arrival
        }
        bar_named(bid);
        if (gtid == 0) red_rel_add1(ctr);    // ONE arrival per block per dir
        // hout DRAM store off the signaling critical path
        if (cl) hout[(size_t)tt * 2048 + (dir << 10) + myu] = h;
    }
}

// ---------------- feats = h1 @ w_out^T + b_out ----------------
__global__ void feats_kernel(const float* __restrict__ h1, const float* __restrict__ wout,
                             const float* __restrict__ bout, float* __restrict__ feats)
{
    __shared__ float red[5][256];
    int t = blockIdx.x, tid = threadIdx.x;
    const float* hrow = h1 + (size_t)t * 2048;
    float p0=0,p1=0,p2=0,p3=0,p4=0;
    for (int k = tid; k < 2048; k += 256) {
        float hv = hrow[k];
        p0 = fmaf(hv, __ldg(wout + 0*2048 + k), p0);
        p1 = fmaf(hv, __ldg(wout + 1*2048 + k), p1);
        p2 = fmaf(hv, __ldg(wout + 2*2048 + k), p2);
        p3 = fmaf(hv, __ldg(wout + 3*2048 + k), p3);
        p4 = fmaf(hv, __ldg(wout + 4*2048 + k), p4);
    }
    red[0][tid]=p0; red[1][tid]=p1; red[2][tid]=p2; red[3][tid]=p3; red[4][tid]=p4;
    __syncthreads();
    if (tid < 5) {
        float s = 0.f;
        for (int i = 0; i < 256; i++) s += red[tid][i];
        feats[t*5 + tid] = s + bout[tid];
    }
}

// ---------------- Viterbi DP + backtrace ----------------
#define NEGV (-10000.0f)
__global__ void viterbi_kernel(const float* __restrict__ feats, const float* __restrict__ trans,
                               float* __restrict__ out, int out_size)
{
    __shared__ unsigned char bp[TT*5];
    __shared__ float fch[256*5];
    const int lane = threadIdx.x;
    float trow[5] = {0,0,0,0,0};
    if (lane < 5) {
        #pragma unroll
        for (int p = 0; p < 5; p++) trow[p] = trans[lane*5 + p];
    }
    float fv[5];
    #pragma unroll
    for (int p = 0; p < 5; p++) fv[p] = (p == 3) ? 0.f : NEGV;

    for (int ch = 0; ch < TT/256; ch++) {
        const float* src = feats + ch*256*5;
        for (int i = lane; i < 256*5; i += 32) fch[i] = src[i];
        __syncwarp();
        for (int s = 0; s < 256; s++) {
            float best = fv[0] + trow[0]; int arg = 0;
            #pragma unroll
            for (int p = 1; p < 5; p++) { float v = fv[p] + trow[p]; if (v > best) { best = v; arg = p; } }
            float fe = (lane < 5) ? fch[s*5 + lane] : 0.f;
            float nv = best + fe;
            if (lane < 5) bp[(ch*256 + s)*5 + lane] = (unsigned char)arg;
            #pragma unroll
            for (int p = 0; p < 5; p++) fv[p] = __shfl_sync(0xFFFFFFFFu, nv, p);
        }
        __syncwarp();
    }
    float term = (lane < 5) ? (fv[lane] + trans[4*5 + lane]) : (4.f*NEGV);
    float t0 = __shfl_sync(0xFFFFFFFFu, term, 0);
    float t1 = __shfl_sync(0xFFFFFFFFu, term, 1);
    float t2 = __shfl_sync(0xFFFFFFFFu, term, 2);
    float t3 = __shfl_sync(0xFFFFFFFFu, term, 3);
    float t4 = __shfl_sync(0xFFFFFFFFu, term, 4);
    if (lane == 0) {
        float best = t0; int lbl = 0;
        if (t1 > best) { best = t1; lbl = 1; }
        if (t2 > best) { best = t2; lbl = 2; }
        if (t3 > best) { best = t3; lbl = 3; }
        if (t4 > best) { best = t4; lbl = 4; }
        if (out_size >= TT + 1) {
            int base = out_size - TT;
            out[0] = best;
            out[base + TT - 1] = (float)lbl;
            for (int t = TT - 2; t >= 0; t--) { lbl = bp[(t+1)*5 + lbl]; out[base + t] = (float)lbl; }
        } else if (out_size >= TT) {
            int base = out_size - TT;
            out[base + TT - 1] = (float)lbl;
            for (int t = TT - 2; t >= 0; t--) { lbl = bp[(t+1)*5 + lbl]; out[base + t] = (float)lbl; }
        } else if (out_size >= 1) {
            out[0] = best;
        }
    }
}

// ---------------- host launch ----------------
extern "C" void kernel_launch(void* const* d_in, const int* in_sizes, int n_in,
                              void* d_out, int out_size)
{
    const float* hours    = (const float*)d_in[0];
    const float* w_ih_l0  = (const float*)d_in[1];
    const float* w_hh_l0  = (const float*)d_in[2];
    const float* b_ih_l0  = (const float*)d_in[3];
    const float* b_hh_l0  = (const float*)d_in[4];
    const float* w_ih_l0r = (const float*)d_in[5];
    const float* w_hh_l0r = (const float*)d_in[6];
    const float* b_ih_l0r = (const float*)d_in[7];
    const float* b_hh_l0r = (const float*)d_in[8];
    const float* w_ih_l1  = (const float*)d_in[9];
    const float* w_hh_l1  = (const float*)d_in[10];
    const float* b_ih_l1  = (const float*)d_in[11];
    const float* b_hh_l1  = (const float*)d_in[12];
    const float* w_ih_l1r = (const float*)d_in[13];
    const float* w_hh_l1r = (const float*)d_in[14];
    const float* b_ih_l1r = (const float*)d_in[15];
    const float* b_hh_l1r = (const float*)d_in[16];
    const float* w_out    = (const float*)d_in[17];
    const float* b_out    = (const float*)d_in[18];
    const float* trans    = (const float*)d_in[19];

    float *xg0, *h0, *h1, *feats;
    cudaGetSymbolAddress((void**)&xg0,   g_xg);
    cudaGetSymbolAddress((void**)&h0,    g_h0);
    cudaGetSymbolAddress((void**)&h1,    g_h1);
    cudaGetSymbolAddress((void**)&feats, g_feats);
    float* xg1 = xg0 + (size_t)TT * G4H;

    cudaFuncSetAttribute(lstm_kernel, cudaFuncAttributeMaxDynamicSharedMemorySize, SMEM_LSTM);

    dim3 gemm_grid(G4H/BN, TT/BM);

    sgemm_bias<<<gemm_grid, 256>>>(hours, w_ih_l0,  b_ih_l0,  b_hh_l0,  xg0, TT, G4H, 512);
    sgemm_bias<<<gemm_grid, 256>>>(hours, w_ih_l0r, b_ih_l0r, b_hh_l0r, xg1, TT, G4H, 512);
    init_kernel<<<16, 256>>>();
    lstm_kernel<<<NBLK, 256, SMEM_LSTM>>>(xg0, xg1, w_hh_l0, w_hh_l0r, h0);

    sgemm_bias<<<gemm_grid, 256>>>(h0, w_ih_l1,  b_ih_l1,  b_hh_l1,  xg0, TT, G4H, 2048);
    sgemm_bias<<<gemm_grid, 256>>>(h0, w_ih_l1r, b_ih_l1r, b_hh_l1r, xg1, TT, G4H, 2048);
    init_kernel<<<16, 256>>>();
    lstm_kernel<<<NBLK, 256, SMEM_LSTM>>>(xg0, xg1, w_hh_l1, w_hh_l1r, h1);

    feats_kernel<<<TT, 256>>>(h1, w_out, b_out, feats);
    viterbi_kernel<<<1, 32>>>(feats, trans, (float*)d_out, out_size);
}

// round 8
// speedup vs baseline: 1.6918x; 1.2538x over previous
#include <cuda_runtime.h>
#include <cuda_bf16.h>
#include <math.h>

#define TT    8192
#define HD    1024
#define G4H   4096
#define NBLK  128               // 128 blocks * 4 warps/dir * 2 units/warp = 1024 units/dir
#define KREG  512               // k < 512 register-resident (4 float4 chunks/lane)
#define KSM   512               // k in [512,1024) in smem
// dynamic smem: weights[8 warps][8 rows][512] + hstage[2][1024]
#define OFF_HS    (8*8*KSM)             // float offset of h stage
#define SMEM_LSTM ((OFF_HS + 2*HD) * 4) // 139264 B

// ---------------- static device scratch ----------------
__device__ float    g_xg[2][TT][G4H];
__device__ float    g_h0[(size_t)TT*2048];
__device__ float    g_h1[(size_t)TT*2048];
__device__ float    g_feats[TT*5];
__device__ float    g_hbuf[2][2][HD];        // [dir][ping][H]
struct Ctr { unsigned v; unsigned pad[31]; };
__device__ Ctr      g_ctr2[2];               // one counter per direction, own 128B line

union F2 { float2 f; unsigned long long u; };

__device__ __forceinline__ unsigned ld_acq(const unsigned* p) {
    unsigned v;
    asm volatile("ld.acquire.gpu.global.u32 %0, [%1];" : "=r"(v) : "l"(p) : "memory");
    return v;
}
__device__ __forceinline__ void red_rel_add1(unsigned* p) {
    asm volatile("red.release.gpu.global.add.u32 [%0], 1;" :: "l"(p) : "memory");
}
__device__ __forceinline__ void bar_named(int id) {
    asm volatile("bar.sync %0, 128;" :: "r"(id) : "memory");
}
__device__ __forceinline__ void fma2(F2& acc, float ax, float ay, float bx, float by) {
    F2 a, b; a.f.x = ax; a.f.y = ay; b.f.x = bx; b.f.y = by;
    asm("fma.rn.f32x2 %0, %1, %2, %0;" : "+l"(acc.u) : "l"(a.u), "l"(b.u));
}

__global__ void init_kernel() {
    int i = blockIdx.x * blockDim.x + threadIdx.x;
    if (i < 2*2*HD) ((float*)g_hbuf)[i] = 0.f;
    if (i < 2) g_ctr2[i].v = 0u;
}

// ---------------- fp32 SGEMM, double-buffered, f32x2 FMA ----------------
#define BM 128
#define BN 128
#define BK 16
__global__ void __launch_bounds__(256) sgemm_bias(
    const float* __restrict__ A, const float* __restrict__ W,
    const float* __restrict__ b1, const float* __restrict__ b2,
    float* __restrict__ C, int M, int N, int K)
{
    __shared__ float As[2][BK][BM+4];
    __shared__ float Bs[2][BK][BN+4];
    const int tid = threadIdx.x;
    const int bm0 = blockIdx.y * BM;
    const int bn0 = blockIdx.x * BN;
    const int tx = tid & 15, ty = tid >> 4;
    const int lrow = tid >> 2;
    const int lc4  = (tid & 3) * 4;

    F2 acc[8][4];
    #pragma unroll
    for (int i = 0; i < 8; i++)
        #pragma unroll
        for (int j = 0; j < 4; j++) acc[i][j].u = 0ull;

    float4 ra[2], rb[2];
    #pragma unroll
    for (int h = 0; h < 2; h++) {
        int row = lrow + h*64;
        ra[h] = *(const float4*)(A + (size_t)(bm0+row)*K + lc4);
        rb[h] = *(const float4*)(W + (size_t)(bn0+row)*K + lc4);
    }
    #pragma unroll
    for (int h = 0; h < 2; h++) {
        int row = lrow + h*64;
        As[0][lc4+0][row] = ra[h].x; As[0][lc4+1][row] = ra[h].y;
        As[0][lc4+2][row] = ra[h].z; As[0][lc4+3][row] = ra[h].w;
        Bs[0][lc4+0][row] = rb[h].x; Bs[0][lc4+1][row] = rb[h].y;
        Bs[0][lc4+2][row] = rb[h].z; Bs[0][lc4+3][row] = rb[h].w;
    }
    __syncthreads();

    int buf = 0;
    for (int k0 = BK; k0 <= K; k0 += BK) {
        if (k0 < K) {
            #pragma unroll
            for (int h = 0; h < 2; h++) {
                int row = lrow + h*64;
                ra[h] = *(const float4*)(A + (size_t)(bm0+row)*K + k0 + lc4);
                rb[h] = *(const float4*)(W + (size_t)(bn0+row)*K + k0 + lc4);
            }
        }
        #pragma unroll
        for (int kk = 0; kk < BK; kk++) {
            float a[8]; F2 bp[4];
            #pragma unroll
            for (int i = 0; i < 8; i++) a[i] = As[buf][kk][ty*8+i];
            #pragma unroll
            for (int j = 0; j < 4; j++) bp[j].f = *(const float2*)&Bs[buf][kk][tx*8 + 2*j];
            #pragma unroll
            for (int i = 0; i < 8; i++) {
                F2 ap; ap.f.x = a[i]; ap.f.y = a[i];
                #pragma unroll
                for (int j = 0; j < 4; j++)
                    asm("fma.rn.f32x2 %0, %1, %2, %0;" : "+l"(acc[i][j].u) : "l"(ap.u), "l"(bp[j].u));
            }
        }
        if (k0 < K) {
            __syncthreads();
            int nb = buf ^ 1;
            #pragma unroll
            for (int h = 0; h < 2; h++) {
                int row = lrow + h*64;
                As[nb][lc4+0][row] = ra[h].x; As[nb][lc4+1][row] = ra[h].y;
                As[nb][lc4+2][row] = ra[h].z; As[nb][lc4+3][row] = ra[h].w;
                Bs[nb][lc4+0][row] = rb[h].x; Bs[nb][lc4+1][row] = rb[h].y;
                Bs[nb][lc4+2][row] = rb[h].z; Bs[nb][lc4+3][row] = rb[h].w;
            }
            __syncthreads();
            buf = nb;
        }
    }
    float bv[8];
    #pragma unroll
    for (int j = 0; j < 8; j++) { int n = bn0 + tx*8 + j; bv[j] = b1[n] + b2[n]; }
    #pragma unroll
    for (int i = 0; i < 8; i++) {
        size_t mrow = (size_t)(bm0 + ty*8 + i) * N;
        #pragma unroll
        for (int j = 0; j < 4; j++) {
            C[mrow + bn0 + tx*8 + 2*j + 0] = acc[i][j].f.x + bv[2*j+0];
            C[mrow + bn0 + tx*8 + 2*j + 1] = acc[i][j].f.y + bv[2*j+1];
        }
    }
}

// ---------------- persistent bidirectional LSTM layer ----------------
// 128 blocks x 8 warps. Warp w: dir=w>>2, gq=w&3, owns units u0=b*8+gq*2 +{0,1}
// = 8 whole gate rows (r = gate*2 + du). Per step:
//   poll warp (gq==0) tight-spins on dir counter, then stages h L2->smem;
//   ONE bar -> per-warp dots (reg+smem weights, f32x2) -> butterfly reduce ->
//   8-lane parallel activations -> lanes 0/1 c/h update + stcg hbuf ->
//   bar -> ONE red.release per block per dir -> hout DRAM store (off path).
__global__ void __launch_bounds__(256, 1) lstm_kernel(
    const float* __restrict__ xgf, const float* __restrict__ xgb,
    const float* __restrict__ whf, const float* __restrict__ whb,
    float* __restrict__ hout)
{
    extern __shared__ float ws[];
    const int tid  = threadIdx.x;
    const int warp = tid >> 5;
    const int lane = tid & 31;
    const int dir  = warp >> 2;
    const int gq   = warp & 3;
    const int gtid = tid & 127;
    const int u0   = blockIdx.x * 8 + gq * 2;

    const float* wh = dir ? whb : whf;
    const float* xg = dir ? xgb : xgf;

    // ---- stage smem weight half (k in [512,1024)), whole block cooperates ----
    for (int idx = tid; idx < 8*8*(KSM/4); idx += 256) {
        int w2 = idx >> 10;                 // warp slot 0..7
        int rr = (idx >> 7) & 7;            // row within warp
        int q  = idx & 127;                 // float4 within KSM
        int unit = blockIdx.x * 8 + (w2 & 3) * 2 + (rr & 1);
        int gate = rr >> 1;
        const float* src = ((w2 >> 2) ? whb : whf) + ((size_t)((gate << 10) + unit)) * HD;
        ((float4*)ws)[idx] = __ldg((const float4*)src + (KREG/4) + q);
    }
    // ---- register weight half (k < 512): wreg[8 rows][4 chunks] ----
    float4 wreg[8][4];
    #pragma unroll
    for (int r = 0; r < 8; r++) {
        int unit = u0 + (r & 1);
        int gate = r >> 1;
        const float4* src = (const float4*)(wh + ((size_t)((gate << 10) + unit)) * HD);
        #pragma unroll
        for (int i = 0; i < 4; i++) wreg[r][i] = __ldg(src + (i << 5) + lane);
    }
    __syncthreads();

    const float4* ws_warp = (const float4*)ws + warp * 8 * (KSM/4);
    float4* hs4 = (float4*)(ws + OFF_HS + dir * HD);
    const bool cl = (lane < 2);
    const int  myu = u0 + lane;             // lanes 0,1
    unsigned* ctr = &g_ctr2[dir].v;
    const int bid = 1 + dir;
    const int du = lane & 1;
    float creg = 0.f;

    #pragma unroll 1
    for (int t = 0; t < TT; t++) {
        const int tt = dir ? (TT-1-t) : t;
        // xg prefetch for lanes 0,1 (DRAM, issued before the wait)
        float xgv0=0.f, xgv1=0.f, xgv2=0.f, xgv3=0.f;
        if (cl) {
            const float* p = xg + (size_t)tt * G4H + myu;
            xgv0 = __ldg(p); xgv1 = __ldg(p+HD); xgv2 = __ldg(p+2*HD); xgv3 = __ldg(p+3*HD);
        }
        // poll warp: tight spin (no nanosleep), then stage h L2 -> smem
        if (gq == 0) {
            const unsigned tgt = (unsigned)t * (unsigned)NBLK;
            while (ld_acq(ctr) < tgt) { }
            const float4* hb4 = (const float4*)&g_hbuf[dir][t & 1][0];
            #pragma unroll
            for (int i = 0; i < 8; i++) hs4[(i << 5) + lane] = __ldcg(hb4 + (i << 5) + lane);
        }
        bar_named(bid);
        // h into registers from smem
        float4 hv[8];
        #pragma unroll
        for (int i = 0; i < 8; i++) hv[i] = hs4[(i << 5) + lane];
        // 8 complete gate-row dots: 4 chunks regs + 4 chunks smem, f32x2
        F2 acc[8];
        #pragma unroll
        for (int r = 0; r < 8; r++) acc[r].u = 0ull;
        #pragma unroll
        for (int r = 0; r < 8; r++) {
            #pragma unroll
            for (int i = 0; i < 4; i++) {
                float4 w = wreg[r][i];
                fma2(acc[r], w.x, w.y, hv[i].x, hv[i].y);
                fma2(acc[r], w.z, w.w, hv[i].z, hv[i].w);
            }
            const float4* w4s = ws_warp + r * (KSM/4);
            #pragma unroll
            for (int i = 0; i < 4; i++) {
                float4 v = w4s[(i << 5) + lane];
                fma2(acc[r], v.x, v.y, hv[4+i].x, hv[4+i].y);
                fma2(acc[r], v.z, v.w, hv[4+i].z, hv[4+i].w);
            }
        }
        // butterfly reduce: every lane gets all 8 row sums
        float v[8];
        #pragma unroll
        for (int r = 0; r < 8; r++) {
            float s = acc[r].f.x + acc[r].f.y;
            #pragma unroll
            for (int off = 16; off; off >>= 1) s += __shfl_xor_sync(0xFFFFFFFFu, s, off);
            v[r] = s;
        }
        // 8-lane parallel activations: lane l computes act of row l (gate l>>1, unit du=l&1)
        float xg0s = __shfl_sync(0xFFFFFFFFu, xgv0, du);
        float xg1s = __shfl_sync(0xFFFFFFFFu, xgv1, du);
        float xg2s = __shfl_sync(0xFFFFFFFFu, xgv2, du);
        float xg3s = __shfl_sync(0xFFFFFFFFu, xgv3, du);
        int gsel = lane >> 1;
        float xgs = (gsel == 0) ? xg0s : (gsel == 1) ? xg1s : (gsel == 2) ? xg2s : xg3s;
        float vsel = v[0];
        vsel = (lane == 1) ? v[1] : vsel;
        vsel = (lane == 2) ? v[2] : vsel;
        vsel = (lane == 3) ? v[3] : vsel;
        vsel = (lane == 4) ? v[4] : vsel;
        vsel = (lane == 5) ? v[5] : vsel;
        vsel = (lane == 6) ? v[6] : vsel;
        vsel = (lane == 7) ? v[7] : vsel;
        float raw = xgs + vsel;
        float act = (gsel == 2) ? tanhf(raw) : 1.f / (1.f + expf(-raw));
        // gather per-unit gates and update (lanes 0,1)
        float ai = __shfl_sync(0xFFFFFFFFu, act, du);
        float af = __shfl_sync(0xFFFFFFFFu, act, 2 + du);
        float ag = __shfl_sync(0xFFFFFFFFu, act, 4 + du);
        float ao = __shfl_sync(0xFFFFFFFFu, act, 6 + du);
        float h = 0.f;
        if (cl) {
            creg = af * creg + ai * ag;
            h = ao * tanhf(creg);
            __stcg(&g_hbuf[dir][(t+1) & 1][myu], h);
        }
        bar_named(bid);
        if (gtid == 0) red_rel_add1(ctr);    // ONE arrival per block per dir
        // hout DRAM store off the signaling critical path
        if (cl) hout[(size_t)tt * 2048 + (dir << 10) + myu] = h;
    }
}

// ---------------- feats = h1 @ w_out^T + b_out ----------------
__global__ void feats_kernel(const float* __restrict__ h1, const float* __restrict__ wout,
                             const float* __restrict__ bout, float* __restrict__ feats)
{
    __shared__ float red[5][256];
    int t = blockIdx.x, tid = threadIdx.x;
    const float* hrow = h1 + (size_t)t * 2048;
    float p0=0,p1=0,p2=0,p3=0,p4=0;
    for (int k = tid; k < 2048; k += 256) {
        float hv = hrow[k];
        p0 = fmaf(hv, __ldg(wout + 0*2048 + k), p0);
        p1 = fmaf(hv, __ldg(wout + 1*2048 + k), p1);
        p2 = fmaf(hv, __ldg(wout + 2*2048 + k), p2);
        p3 = fmaf(hv, __ldg(wout + 3*2048 + k), p3);
        p4 = fmaf(hv, __ldg(wout + 4*2048 + k), p4);
    }
    red[0][tid]=p0; red[1][tid]=p1; red[2][tid]=p2; red[3][tid]=p3; red[4][tid]=p4;
    __syncthreads();
    if (tid < 5) {
        float s = 0.f;
        for (int i = 0; i < 256; i++) s += red[tid][i];
        feats[t*5 + tid] = s + bout[tid];
    }
}

// ---------------- Viterbi DP + backtrace ----------------
#define NEGV (-10000.0f)
__global__ void viterbi_kernel(const float* __restrict__ feats, const float* __restrict__ trans,
                               float* __restrict__ out, int out_size)
{
    __shared__ unsigned char bp[TT*5];
    __shared__ float fch[256*5];
    const int lane = threadIdx.x;
    float trow[5] = {0,0,0,0,0};
    if (lane < 5) {
        #pragma unroll
        for (int p = 0; p < 5; p++) trow[p] = trans[lane*5 + p];
    }
    float fv[5];
    #pragma unroll
    for (int p = 0; p < 5; p++) fv[p] = (p == 3) ? 0.f : NEGV;

    for (int ch = 0; ch < TT/256; ch++) {
        const float* src = feats + ch*256*5;
        for (int i = lane; i < 256*5; i += 32) fch[i] = src[i];
        __syncwarp();
        for (int s = 0; s < 256; s++) {
            float best = fv[0] + trow[0]; int arg = 0;
            #pragma unroll
            for (int p = 1; p < 5; p++) { float v = fv[p] + trow[p]; if (v > best) { best = v; arg = p; } }
            float fe = (lane < 5) ? fch[s*5 + lane] : 0.f;
            float nv = best + fe;
            if (lane < 5) bp[(ch*256 + s)*5 + lane] = (unsigned char)arg;
            #pragma unroll
            for (int p = 0; p < 5; p++) fv[p] = __shfl_sync(0xFFFFFFFFu, nv, p);
        }
        __syncwarp();
    }
    float term = (lane < 5) ? (fv[lane] + trans[4*5 + lane]) : (4.f*NEGV);
    float t0 = __shfl_sync(0xFFFFFFFFu, term, 0);
    float t1 = __shfl_sync(0xFFFFFFFFu, term, 1);
    float t2 = __shfl_sync(0xFFFFFFFFu, term, 2);
    float t3 = __shfl_sync(0xFFFFFFFFu, term, 3);
    float t4 = __shfl_sync(0xFFFFFFFFu, term, 4);
    if (lane == 0) {
        float best = t0; int lbl = 0;
        if (t1 > best) { best = t1; lbl = 1; }
        if (t2 > best) { best = t2; lbl = 2; }
        if (t3 > best) { best = t3; lbl = 3; }
        if (t4 > best) { best = t4; lbl = 4; }
        if (out_size >= TT + 1) {
            int base = out_size - TT;
            out[0] = best;
            out[base + TT - 1] = (float)lbl;
            for (int t = TT - 2; t >= 0; t--) { lbl = bp[(t+1)*5 + lbl]; out[base + t] = (float)lbl; }
        } else if (out_size >= TT) {
            int base = out_size - TT;
            out[base + TT - 1] = (float)lbl;
            for (int t = TT - 2; t >= 0; t--) { lbl = bp[(t+1)*5 + lbl]; out[base + t] = (float)lbl; }
        } else if (out_size >= 1) {
            out[0] = best;
        }
    }
}

// ---------------- host launch ----------------
extern "C" void kernel_launch(void* const* d_in, const int* in_sizes, int n_in,
                              void* d_out, int out_size)
{
    const float* hours    = (const float*)d_in[0];
    const float* w_ih_l0  = (const float*)d_in[1];
    const float* w_hh_l0  = (const float*)d_in[2];
    const float* b_ih_l0  = (const float*)d_in[3];
    const float* b_hh_l0  = (const float*)d_in[4];
    const float* w_ih_l0r = (const float*)d_in[5];
    const float* w_hh_l0r = (const float*)d_in[6];
    const float* b_ih_l0r = (const float*)d_in[7];
    const float* b_hh_l0r = (const float*)d_in[8];
    const float* w_ih_l1  = (const float*)d_in[9];
    const float* w_hh_l1  = (const float*)d_in[10];
    const float* b_ih_l1  = (const float*)d_in[11];
    const float* b_hh_l1  = (const float*)d_in[12];
    const float* w_ih_l1r = (const float*)d_in[13];
    const float* w_hh_l1r = (const float*)d_in[14];
    const float* b_ih_l1r = (const float*)d_in[15];
    const float* b_hh_l1r = (const float*)d_in[16];
    const float* w_out    = (const float*)d_in[17];
    const float* b_out    = (const float*)d_in[18];
    const float* trans    = (const float*)d_in[19];

    float *xg0, *h0, *h1, *feats;
    cudaGetSymbolAddress((void**)&xg0,   g_xg);
    cudaGetSymbolAddress((void**)&h0,    g_h0);
    cudaGetSymbolAddress((void**)&h1,    g_h1);
    cudaGetSymbolAddress((void**)&feats, g_feats);
    float* xg1 = xg0 + (size_t)TT * G4H;

    cudaFuncSetAttribute(lstm_kernel, cudaFuncAttributeMaxDynamicSharedMemorySize, SMEM_LSTM);

    dim3 gemm_grid(G4H/BN, TT/BM);

    sgemm_bias<<<gemm_grid, 256>>>(hours, w_ih_l0,  b_ih_l0,  b_hh_l0,  xg0, TT, G4H, 512);
    sgemm_bias<<<gemm_grid, 256>>>(hours, w_ih_l0r, b_ih_l0r, b_hh_l0r, xg1, TT, G4H, 512);
    init_kernel<<<16, 256>>>();
    lstm_kernel<<<NBLK, 256, SMEM_LSTM>>>(xg0, xg1, w_hh_l0, w_hh_l0r, h0);

    sgemm_bias<<<gemm_grid, 256>>>(h0, w_ih_l1,  b_ih_l1,  b_hh_l1,  xg0, TT, G4H, 2048);
    sgemm_bias<<<gemm_grid, 256>>>(h0, w_ih_l1r, b_ih_l1r, b_hh_l1r, xg1, TT, G4H, 2048);
    init_kernel<<<16, 256>>>();
    lstm_kernel<<<NBLK, 256, SMEM_LSTM>>>(xg0, xg1, w_hh_l1, w_hh_l1r, h1);

    feats_kernel<<<TT, 256>>>(h1, w_out, b_out, feats);
    viterbi_kernel<<<1, 32>>>(feats, trans, (float*)d_out, out_size);
}